// round 4
// baseline (speedup 1.0000x reference)
#include <cuda_runtime.h>

// Problem constants (from reference): x (B,N,1) f32, indices (2,NNZ) i32,
// values (NNZ,) f32, bias (M,1) f32  ->  out (B,M,1) f32
#define NN   100000
#define MM   100000
#define NNZ  3200000
#define BB   32

// Scratch: transposed activations and accumulator (batch-contiguous layout).
// xt[n*32 + b] = x[b*N + n];  yt[m*32 + b] accumulates, then transposed out.
__device__ float g_xt[(size_t)NN * BB];
__device__ float g_yt[(size_t)MM * BB];

// ---------------------------------------------------------------------------
// Kernel 1: tiled transpose x (B,N) -> xt (N,B), and zero yt (M == N here,
// guarded independently). Fully coalesced on both sides via 32x33 smem tile.
// ---------------------------------------------------------------------------
__global__ void k_transpose_in(const float* __restrict__ x) {
    __shared__ float tile[32][33];
    const int n0 = blockIdx.x * 32;
    const int tx = threadIdx.x;   // fast dim
    const int ty = threadIdx.y;

    // Load: x[b=ty][n0+tx]  (coalesced over tx)
    {
        const int n = n0 + tx;
        if (n < NN) tile[ty][tx] = x[(size_t)ty * NN + n];
    }
    __syncthreads();

    // Store: xt[(n0+ty)*32 + tx]  (coalesced over tx = b)
    {
        const int n = n0 + ty;
        if (n < NN)  g_xt[(size_t)n * BB + tx] = tile[tx][ty];
        if (n < MM)  g_yt[(size_t)n * BB + tx] = 0.0f;   // zero accumulator
    }
}

// ---------------------------------------------------------------------------
// Kernel 2: edge scatter. 8 threads per edge; each thread handles a float4 of
// batches. Gather is one coalesced 128B line from xt; accumulate via vector
// reduction red.global.add.v4.f32 (no return value, 8 RED ops per edge).
// ---------------------------------------------------------------------------
__global__ void k_scatter(const int* __restrict__ indices,
                          const float* __restrict__ values) {
    const long long t = (long long)blockIdx.x * blockDim.x + threadIdx.x;
    const long long e = t >> 3;        // edge id
    const int       q = (int)(t & 7);  // which float4 of the 32 batches
    if (e >= NNZ) return;

    const int   src = indices[e];
    const int   dst = indices[(long long)NNZ + e];
    const float v   = values[e];

    const float4 xv = reinterpret_cast<const float4*>(g_xt)[(size_t)src * 8 + q];
    const float4 c  = make_float4(v * xv.x, v * xv.y, v * xv.z, v * xv.w);

    float4* p = reinterpret_cast<float4*>(g_yt) + (size_t)dst * 8 + q;
    asm volatile("red.global.add.v4.f32 [%0], {%1, %2, %3, %4};"
                 :: "l"(p), "f"(c.x), "f"(c.y), "f"(c.z), "f"(c.w)
                 : "memory");
}

// ---------------------------------------------------------------------------
// Kernel 3: tiled transpose yt (M,B) -> out (B,M), adding bias[m].
// ---------------------------------------------------------------------------
__global__ void k_transpose_out(float* __restrict__ out,
                                const float* __restrict__ bias) {
    __shared__ float tile[32][33];
    const int m0 = blockIdx.x * 32;
    const int tx = threadIdx.x;
    const int ty = threadIdx.y;

    // Load: yt[(m0+ty)*32 + tx]  (coalesced over tx = b)
    {
        const int m = m0 + ty;
        if (m < MM) tile[ty][tx] = g_yt[(size_t)m * BB + tx];
    }
    __syncthreads();

    // Store: out[b=ty][m0+tx] = tile[tx][ty] + bias[m0+tx]  (coalesced over tx)
    {
        const int m = m0 + tx;
        if (m < MM) out[(size_t)ty * MM + m] = tile[tx][ty] + bias[m];
    }
}

extern "C" void kernel_launch(void* const* d_in, const int* in_sizes, int n_in,
                              void* d_out, int out_size) {
    const float* x       = (const float*)d_in[0];   // (B, N, 1)
    const int*   indices = (const int*)  d_in[1];   // (2, NNZ)
    const float* values  = (const float*)d_in[2];   // (NNZ,)
    const float* bias    = (const float*)d_in[3];   // (M, 1)
    float*       out     = (float*)d_out;           // (B, M, 1)

    (void)in_sizes; (void)n_in; (void)out_size;

    // 1) transpose x -> xt, zero yt
    {
        dim3 blk(32, 32);
        dim3 grd((NN + 31) / 32);
        k_transpose_in<<<grd, blk>>>(x);
    }

    // 2) edge scatter: NNZ * 8 threads
    {
        const long long total = (long long)NNZ * 8;
        const int threads = 256;
        const int blocks = (int)((total + threads - 1) / threads);
        k_scatter<<<blocks, threads>>>(indices, values);
    }

    // 3) transpose yt -> out (+bias)
    {
        dim3 blk(32, 32);
        dim3 grd((MM + 31) / 32);
        k_transpose_out<<<grd, blk>>>(out, bias);
    }
}